// round 17
// baseline (speedup 1.0000x reference)
#include <cuda_runtime.h>
#include <cuda_fp16.h>
#include <cstdint>

#define B_ 2
#define N_ 2048
#define L_ 2048
#define D_ 1024
#define H_ 16
#define HD_ 64
#define LOG2E 1.4426950408889634f
#define SCALE_Q (0.125f * LOG2E)
#define MASKBIAS (-2.0e30f)
#define MINIT (-1.0e30f)

__device__ __half g_Xq[(size_t)B_ * N_ * D_];
__device__ __half g_Xkv[(size_t)B_ * L_ * D_];
__device__ __half g_WTh[4 * 1024 * 1024];            // [z][n][k]
__device__ __half g_Q[(size_t)B_ * H_ * N_ * HD_];   // *SCALE_Q
__device__ __half g_K[(size_t)B_ * H_ * L_ * HD_];
__device__ __half g_VT[(size_t)B_ * H_ * HD_ * L_];  // [bh][d][l]
__device__ __half g_O[(size_t)B_ * N_ * D_];
__device__ unsigned char g_mask[B_ * L_];

// dataflow readiness counters (zeroed by reset kernel each call)
__device__ int g_cQ[32 * 8];   // per (m_idx, n_idx) Q tile flag
__device__ int g_cK[2 * 8];    // per (b, n_idx) K count -> 16
__device__ int g_cV[2 * 8];    // per (b, n_idx) V count -> 16
__device__ int g_cA[32];       // per row-block attention count -> 16
__device__ int g_cX[32];       // per 128-row x-convert count -> 128
__device__ int g_cW[4 * 8];    // per (z, n_idx) weight-transpose count -> 128
__device__ int g_cM[1];        // mask ready flag

__device__ __forceinline__ float ex2f(float x) {
    float r; asm("ex2.approx.ftz.f32 %0, %1;" : "=f"(r) : "f"(x)); return r;
}
__device__ __forceinline__ uint32_t h2pack(float lo, float hi) {
    __half2 h = __floats2half2_rn(lo, hi);
    return *(uint32_t*)&h;
}
__device__ __forceinline__ uint32_t smem_u32(const void* p) {
    uint32_t a;
    asm("{ .reg .u64 t; cvta.to.shared.u64 t, %1; cvt.u32.u64 %0, t; }" : "=r"(a) : "l"(p));
    return a;
}
__device__ __forceinline__ void cpa16(uint32_t dst, const void* src) {
    asm volatile("cp.async.cg.shared.global [%0], [%1], 16;" :: "r"(dst), "l"(src));
}
#define CPA_COMMIT() asm volatile("cp.async.commit_group;" ::: "memory")
#define CPA_WAIT0()  asm volatile("cp.async.wait_group 0;" ::: "memory")

#define MMA_F16(C, A, Bf) \
    asm volatile("mma.sync.aligned.m16n8k16.row.col.f32.f16.f16.f32 " \
        "{%0,%1,%2,%3},{%4,%5,%6,%7},{%8,%9},{%0,%1,%2,%3};" \
        : "+f"((C)[0]), "+f"((C)[1]), "+f"((C)[2]), "+f"((C)[3]) \
        : "r"((A)[0]), "r"((A)[1]), "r"((A)[2]), "r"((A)[3]), "r"((Bf)[0]), "r"((Bf)[1]))

__device__ __forceinline__ void spin_ge(int* p, int target) {
    while (atomicAdd(p, 0) < target) __nanosleep(64);
}

// ---------------------------------------------------------------------------
__global__ void reset_cnt()
{
    int t = threadIdx.x;
    if (t < 256) g_cQ[t] = 0;
    if (t < 16) { g_cK[t] = 0; g_cV[t] = 0; }
    if (t < 32) { g_cA[t] = 0; g_cX[t] = 0; g_cW[t] = 0; }
    if (t == 0) g_cM[0] = 0;
}

// ---------------------------------------------------------------------------
// GEMM tile body (CTA 128x128, 4 warps, cp.async double-buffered, BK=64).
// ---------------------------------------------------------------------------
#define SP2 36
#define TB_SZ (128 * SP2)
#define PR_SMEM (4 * TB_SZ * 4)

__device__ __forceinline__ void proj_body(
    int mode, int m_idx, int n_idx, uint32_t* smp,
    const float* b0, const float* b1, const float* b2, const float* b3,
    float* Cout)
{
    const uint32_t sbase = smem_u32(smp);
    const __half* Ah = (mode == 0) ? g_Xq : (mode == 3) ? g_O : g_Xkv;
    const __half* Wh = g_WTh + ((size_t)mode << 20);
    const float* bias = (mode == 0) ? b0 : (mode == 1) ? b1 : (mode == 2) ? b2 : b3;

    const int tid = threadIdx.x;
    const int lane = tid & 31, wid = tid >> 5;
    const int g = lane >> 2, t = lane & 3;
    const int wm = wid & 1, wn = wid >> 1;
    const int m0 = m_idx * 128, n0 = n_idx * 128;
    const int crow = tid >> 3, cc = tid & 7;

    float c[4][8][4];
#pragma unroll
    for (int i = 0; i < 4; i++)
#pragma unroll
        for (int j = 0; j < 8; j++)
#pragma unroll
            for (int k = 0; k < 4; k++) c[i][j][k] = 0.0f;

#pragma unroll 1
    for (int kt = 0; kt < 16; kt++) {
        if (kt == 0) {
            const uint32_t aoff = 0, boff = 2 * TB_SZ;
#pragma unroll
            for (int q = 0; q < 8; q++) {
                int row = crow + 16 * q;
                cpa16(sbase + (aoff + row * SP2 + cc * 4) * 4,
                      Ah + (size_t)(m0 + row) * D_ + cc * 8);
                cpa16(sbase + (boff + row * SP2 + cc * 4) * 4,
                      Wh + (size_t)(n0 + row) * D_ + cc * 8);
            }
            CPA_COMMIT();
        }
        CPA_WAIT0();
        __syncthreads();
        if (kt < 15) {
            const int s = (kt + 1) & 1;
            const uint32_t aoff = s * TB_SZ, boff = 2 * TB_SZ + s * TB_SZ;
#pragma unroll
            for (int q = 0; q < 8; q++) {
                int row = crow + 16 * q;
                cpa16(sbase + (aoff + row * SP2 + cc * 4) * 4,
                      Ah + (size_t)(m0 + row) * D_ + (kt + 1) * 64 + cc * 8);
                cpa16(sbase + (boff + row * SP2 + cc * 4) * 4,
                      Wh + (size_t)(n0 + row) * D_ + (kt + 1) * 64 + cc * 8);
            }
            CPA_COMMIT();
        }
        const uint32_t* As = smp + (kt & 1) * TB_SZ;
        const uint32_t* Bs = smp + 2 * TB_SZ + (kt & 1) * TB_SZ;
#pragma unroll
        for (int kb = 0; kb < 4; kb++) {
            const int k0 = 8 * kb;
            uint32_t a[4][4];
#pragma unroll
            for (int mt = 0; mt < 4; mt++) {
                int r = wm * 64 + mt * 16 + g;
                a[mt][0] = As[r * SP2 + k0 + t];
                a[mt][1] = As[(r + 8) * SP2 + k0 + t];
                a[mt][2] = As[r * SP2 + k0 + t + 4];
                a[mt][3] = As[(r + 8) * SP2 + k0 + t + 4];
            }
#pragma unroll
            for (int nt = 0; nt < 8; nt++) {
                int n = wn * 64 + nt * 8 + g;
                uint32_t b[2];
                b[0] = Bs[n * SP2 + k0 + t];
                b[1] = Bs[n * SP2 + k0 + t + 4];
                MMA_F16(c[0][nt], a[0], b);
                MMA_F16(c[1][nt], a[1], b);
                MMA_F16(c[2][nt], a[2], b);
                MMA_F16(c[3][nt], a[3], b);
            }
        }
    }

    if (mode == 2) {
        __syncthreads();
        __half* stg = (__half*)smp;      // 128 cols x 136 halves
#pragma unroll
        for (int mt = 0; mt < 4; mt++) {
            int r0l = wm * 64 + mt * 16 + g;
            int r1l = r0l + 8;
#pragma unroll
            for (int nt = 0; nt < 8; nt++) {
                int cl = wn * 64 + nt * 8 + 2 * t;
                float2 bb = *(const float2*)&bias[n0 + cl];
                stg[cl * 136 + r0l]       = __float2half(c[mt][nt][0] + bb.x);
                stg[(cl + 1) * 136 + r0l] = __float2half(c[mt][nt][1] + bb.y);
                stg[cl * 136 + r1l]       = __float2half(c[mt][nt][2] + bb.x);
                stg[(cl + 1) * 136 + r1l] = __float2half(c[mt][nt][3] + bb.y);
            }
        }
        __syncthreads();
        int cgl = n0 + tid;
        int hh = cgl >> 6, hd = cgl & 63;
        int bb2 = m0 >> 11, l0 = m0 & 2047;
        __half* dst = g_VT + ((size_t)(bb2 * H_ + hh) * HD_ + hd) * L_ + l0;
#pragma unroll
        for (int q = 0; q < 16; q++)
            *(uint4*)(dst + q * 8) = *(const uint4*)&stg[tid * 136 + q * 8];
        __threadfence();
        __syncthreads();
        if (tid == 0) atomicAdd(&g_cV[(m_idx >> 4) * 8 + n_idx], 1);
        return;
    }

#pragma unroll
    for (int mt = 0; mt < 4; mt++) {
        int r0 = m0 + wm * 64 + mt * 16 + g;
        int r1 = r0 + 8;
#pragma unroll
        for (int nt = 0; nt < 8; nt++) {
            int col = n0 + wn * 64 + nt * 8 + 2 * t;
            float2 bb = *(const float2*)&bias[col];
            float v00 = c[mt][nt][0] + bb.x, v01 = c[mt][nt][1] + bb.y;
            float v10 = c[mt][nt][2] + bb.x, v11 = c[mt][nt][3] + bb.y;
            if (mode == 0) {
                v00 *= SCALE_Q; v01 *= SCALE_Q; v10 *= SCALE_Q; v11 *= SCALE_Q;
            }
            if (mode == 3) {
                *(float2*)&Cout[(size_t)r0 * D_ + col] = make_float2(v00, v01);
                *(float2*)&Cout[(size_t)r1 * D_ + col] = make_float2(v10, v11);
            } else {
                __half* dst = (mode == 0) ? g_Q : g_K;
                int hh = col >> 6, hd = col & 63;
                {
                    int bb2 = r0 >> 11, n = r0 & 2047;
                    *(__half2*)(dst + (((size_t)(bb2 * H_ + hh)) * 2048 + n) * HD_ + hd) =
                        __floats2half2_rn(v00, v01);
                }
                {
                    int bb2 = r1 >> 11, n = r1 & 2047;
                    *(__half2*)(dst + (((size_t)(bb2 * H_ + hh)) * 2048 + n) * HD_ + hd) =
                        __floats2half2_rn(v10, v11);
                }
            }
        }
    }
    if (mode != 3) {
        __threadfence();
        __syncthreads();
        if (tid == 0) {
            if (mode == 0) atomicAdd(&g_cQ[m_idx * 8 + n_idx], 1);
            else           atomicAdd(&g_cK[(m_idx >> 4) * 8 + n_idx], 1);
        }
    }
}

// ---------------------------------------------------------------------------
// Attention tile body (128q x (b,h); 4 warps; cp.async K/V double-buffered).
// ---------------------------------------------------------------------------
#define SK2 36
#define QS_SZ (128 * SK2)
#define KV_SZ (64 * SK2)

__device__ __forceinline__ void attn_body(int qt, int bh, uint32_t* smA)
{
    uint32_t* Qs = smA;
    uint32_t* Ksb = smA + QS_SZ;
    uint32_t* Vsb = smA + QS_SZ + 2 * KV_SZ;
    float* Mbb = (float*)(smA + QS_SZ + 4 * KV_SZ);
    const uint32_t sbase = smem_u32(smA);

    const int tid = threadIdx.x;
    const int lane = tid & 31, wid = tid >> 5;
    const int g = lane >> 2, t = lane & 3;
    const int b = bh >> 4, h = bh & 15;

    const __half* Qp = g_Q + ((size_t)bh * N_ + qt * 128) * HD_;
    const __half* Kp = g_K + (size_t)bh * L_ * HD_;
    const __half* Vtp = g_VT + (size_t)bh * HD_ * L_;
    const unsigned char* mp = g_mask + b * L_;

#pragma unroll
    for (int q = 0; q < 8; q++) {
        int idx = tid + 128 * q;
        int row = idx >> 3, cu = (idx & 7) * 4;
        *(uint4*)&Qs[row * SK2 + cu] = *(const uint4*)(Qp + (size_t)row * HD_ + (idx & 7) * 8);
    }

    auto issue_kv = [&](int tt, int s) {
#pragma unroll
        for (int q = 0; q < 4; q++) {
            int idx = tid + 128 * q;
            int row = idx >> 3, ch = idx & 7;
            cpa16(sbase + (QS_SZ + s * KV_SZ + row * SK2 + ch * 4) * 4,
                  Kp + (size_t)(tt * 64 + row) * HD_ + ch * 8);
            cpa16(sbase + (QS_SZ + 2 * KV_SZ + s * KV_SZ + row * SK2 + ch * 4) * 4,
                  Vtp + (size_t)row * L_ + tt * 64 + ch * 8);
        }
    };
    auto load_mb = [&](int tt, int s) {
        if (tid < 16) {
            uchar4 mv = *(const uchar4*)(mp + tt * 64 + tid * 4);
            float* Mb = Mbb + s * 64;
            Mb[tid * 4 + 0] = mv.x ? MASKBIAS : 0.0f;
            Mb[tid * 4 + 1] = mv.y ? MASKBIAS : 0.0f;
            Mb[tid * 4 + 2] = mv.z ? MASKBIAS : 0.0f;
            Mb[tid * 4 + 3] = mv.w ? MASKBIAS : 0.0f;
        }
    };

    issue_kv(0, 0); CPA_COMMIT();
    load_mb(0, 0);

    float m[4], l[4];
    float oc[2][8][4];
#pragma unroll
    for (int s = 0; s < 4; s++) { m[s] = MINIT; l[s] = 0.0f; }
#pragma unroll
    for (int mt = 0; mt < 2; mt++)
#pragma unroll
        for (int nt = 0; nt < 8; nt++)
#pragma unroll
            for (int j = 0; j < 4; j++) oc[mt][nt][j] = 0.0f;

    const int R = wid * 32;
    const int NT = L_ / 64;

#pragma unroll 1
    for (int tt = 0; tt < NT; tt++) {
        const int cb = tt & 1;
        CPA_WAIT0();
        __syncthreads();
        if (tt + 1 < NT) issue_kv(tt + 1, cb ^ 1);
        CPA_COMMIT();
        if (tt + 1 < NT) load_mb(tt + 1, cb ^ 1);

        const uint32_t* Ks = Ksb + cb * KV_SZ;
        const uint32_t* Vs = Vsb + cb * KV_SZ;
        const float* Mb = Mbb + cb * 64;

        float sc[2][8][4];
#pragma unroll
        for (int mt = 0; mt < 2; mt++)
#pragma unroll
            for (int nt = 0; nt < 8; nt++)
#pragma unroll
                for (int j = 0; j < 4; j++) sc[mt][nt][j] = 0.0f;
#pragma unroll
        for (int kb = 0; kb < 4; kb++) {
            const int k0 = 8 * kb;
            uint32_t aq[2][4];
#pragma unroll
            for (int mt = 0; mt < 2; mt++) {
                int r = R + mt * 16 + g;
                aq[mt][0] = Qs[r * SK2 + k0 + t];
                aq[mt][1] = Qs[(r + 8) * SK2 + k0 + t];
                aq[mt][2] = Qs[r * SK2 + k0 + t + 4];
                aq[mt][3] = Qs[(r + 8) * SK2 + k0 + t + 4];
            }
#pragma unroll
            for (int nt = 0; nt < 8; nt++) {
                int n = nt * 8 + g;
                uint32_t bk[2];
                bk[0] = Ks[n * SK2 + k0 + t];
                bk[1] = Ks[n * SK2 + k0 + t + 4];
                MMA_F16(sc[0][nt], aq[0], bk);
                MMA_F16(sc[1][nt], aq[1], bk);
            }
        }

#pragma unroll
        for (int nt = 0; nt < 8; nt++) {
            float2 mb = *(const float2*)&Mb[nt * 8 + 2 * t];
#pragma unroll
            for (int mt = 0; mt < 2; mt++) {
                sc[mt][nt][0] += mb.x; sc[mt][nt][1] += mb.y;
                sc[mt][nt][2] += mb.x; sc[mt][nt][3] += mb.y;
            }
        }

        float tm[4];
#pragma unroll
        for (int s = 0; s < 4; s++) tm[s] = -3.0e38f;
#pragma unroll
        for (int mt = 0; mt < 2; mt++)
#pragma unroll
            for (int nt = 0; nt < 8; nt++) {
                tm[mt * 2 + 0] = fmaxf(tm[mt * 2 + 0], fmaxf(sc[mt][nt][0], sc[mt][nt][1]));
                tm[mt * 2 + 1] = fmaxf(tm[mt * 2 + 1], fmaxf(sc[mt][nt][2], sc[mt][nt][3]));
            }
#pragma unroll
        for (int off = 1; off < 4; off <<= 1)
#pragma unroll
            for (int s = 0; s < 4; s++)
                tm[s] = fmaxf(tm[s], __shfl_xor_sync(0xffffffffu, tm[s], off));

        float al[4], rs[4];
#pragma unroll
        for (int s = 0; s < 4; s++) {
            float mn = fmaxf(m[s], tm[s]);
            al[s] = ex2f(m[s] - mn);
            m[s] = mn;
            rs[s] = 0.0f;
        }
#pragma unroll
        for (int mt = 0; mt < 2; mt++)
#pragma unroll
            for (int nt = 0; nt < 8; nt++) {
                sc[mt][nt][0] = ex2f(sc[mt][nt][0] - m[mt * 2 + 0]);
                sc[mt][nt][1] = ex2f(sc[mt][nt][1] - m[mt * 2 + 0]);
                sc[mt][nt][2] = ex2f(sc[mt][nt][2] - m[mt * 2 + 1]);
                sc[mt][nt][3] = ex2f(sc[mt][nt][3] - m[mt * 2 + 1]);
                rs[mt * 2 + 0] += sc[mt][nt][0] + sc[mt][nt][1];
                rs[mt * 2 + 1] += sc[mt][nt][2] + sc[mt][nt][3];
            }
#pragma unroll
        for (int off = 1; off < 4; off <<= 1)
#pragma unroll
            for (int s = 0; s < 4; s++)
                rs[s] += __shfl_xor_sync(0xffffffffu, rs[s], off);
#pragma unroll
        for (int s = 0; s < 4; s++) l[s] = l[s] * al[s] + rs[s];
#pragma unroll
        for (int mt = 0; mt < 2; mt++)
#pragma unroll
            for (int nt = 0; nt < 8; nt++) {
                oc[mt][nt][0] *= al[mt * 2 + 0]; oc[mt][nt][1] *= al[mt * 2 + 0];
                oc[mt][nt][2] *= al[mt * 2 + 1]; oc[mt][nt][3] *= al[mt * 2 + 1];
            }

#pragma unroll
        for (int j = 0; j < 4; j++) {
            const int k0 = 8 * j;
            uint32_t ap[2][4];
#pragma unroll
            for (int mt = 0; mt < 2; mt++) {
                ap[mt][0] = h2pack(sc[mt][2 * j][0], sc[mt][2 * j][1]);
                ap[mt][1] = h2pack(sc[mt][2 * j][2], sc[mt][2 * j][3]);
                ap[mt][2] = h2pack(sc[mt][2 * j + 1][0], sc[mt][2 * j + 1][1]);
                ap[mt][3] = h2pack(sc[mt][2 * j + 1][2], sc[mt][2 * j + 1][3]);
            }
#pragma unroll
            for (int nt = 0; nt < 8; nt++) {
                int n = nt * 8 + g;
                uint32_t bv[2];
                bv[0] = Vs[n * SK2 + k0 + t];
                bv[1] = Vs[n * SK2 + k0 + t + 4];
                MMA_F16(oc[0][nt], ap[0], bv);
                MMA_F16(oc[1][nt], ap[1], bv);
            }
        }
    }

    float inv[4];
#pragma unroll
    for (int s = 0; s < 4; s++) inv[s] = 1.0f / l[s];
#pragma unroll
    for (int mt = 0; mt < 2; mt++) {
        int n0r = qt * 128 + R + mt * 16 + g;
        int n1r = n0r + 8;
#pragma unroll
        for (int nt = 0; nt < 8; nt++) {
            int cc = nt * 8 + 2 * t;
            *(__half2*)(g_O + ((size_t)(b * N_ + n0r)) * D_ + h * HD_ + cc) =
                __floats2half2_rn(oc[mt][nt][0] * inv[mt * 2 + 0],
                                  oc[mt][nt][1] * inv[mt * 2 + 0]);
            *(__half2*)(g_O + ((size_t)(b * N_ + n1r)) * D_ + h * HD_ + cc) =
                __floats2half2_rn(oc[mt][nt][2] * inv[mt * 2 + 1],
                                  oc[mt][nt][3] * inv[mt * 2 + 1]);
        }
    }
    __threadfence();
    __syncthreads();
    if (tid == 0) atomicAdd(&g_cA[b * 16 + qt], 1);
}

// ---------------------------------------------------------------------------
// Megakernel: [0,4096) x-cvt rows; [4096,8192) weight transpose tiles
// (n-column-major so QKV deps finish first); 8192 mask; [8193,8961) QKV;
// [8961,9473) attention; [9473,9729) out-projection.
// ---------------------------------------------------------------------------
__global__ void __launch_bounds__(128, 2)
mega(const float* __restrict__ xq, const float* __restrict__ xkv,
     const float* __restrict__ w0, const float* __restrict__ w1,
     const float* __restrict__ w2, const float* __restrict__ w3,
     const void* __restrict__ mraw,
     const float* __restrict__ b0, const float* __restrict__ b1,
     const float* __restrict__ b2, const float* __restrict__ b3,
     float* __restrict__ Cout)
{
    extern __shared__ uint32_t smp[];
    const int id = blockIdx.x;
    const int tid = threadIdx.x;

    if (id < 4096) {
        // convert one 1024-element row of x_q and x_kv to half
        int base = id * 256 + tid * 2;   // float4 index
        float4 a0 = ((const float4*)xq)[base];
        float4 a1 = ((const float4*)xq)[base + 1];
        float4 k0 = ((const float4*)xkv)[base];
        float4 k1 = ((const float4*)xkv)[base + 1];
        __half2* q2 = (__half2*)g_Xq;
        __half2* k2 = (__half2*)g_Xkv;
        q2[2 * base + 0] = __floats2half2_rn(a0.x, a0.y);
        q2[2 * base + 1] = __floats2half2_rn(a0.z, a0.w);
        q2[2 * base + 2] = __floats2half2_rn(a1.x, a1.y);
        q2[2 * base + 3] = __floats2half2_rn(a1.z, a1.w);
        k2[2 * base + 0] = __floats2half2_rn(k0.x, k0.y);
        k2[2 * base + 1] = __floats2half2_rn(k0.z, k0.w);
        k2[2 * base + 2] = __floats2half2_rn(k1.x, k1.y);
        k2[2 * base + 3] = __floats2half2_rn(k1.z, k1.w);
        __threadfence();
        __syncthreads();
        if (tid == 0) atomicAdd(&g_cX[id >> 7], 1);
    } else if (id < 8192) {
        // transpose+convert one 32x32 weight tile; n-major ordering
        int idx = id - 4096;
        int z = idx >> 10, r = idx & 1023;
        int bxt = (r >> 5) * 32;   // dst row (n) — outer so n-columns finish first
        int byt = (r & 31) * 32;   // dst col (k)
        const float* src = (z == 0) ? w0 : (z == 1) ? w1 : (z == 2) ? w2 : w3;
        __half* dst = g_WTh + ((size_t)z << 20);
        float* t = (float*)smp;    // [32][33]
        int x = tid & 31, y0 = tid >> 5;   // 32 x 4
#pragma unroll
        for (int i = 0; i < 32; i += 4)
            t[(y0 + i) * 33 + x] = src[(size_t)(byt + y0 + i) * 1024 + bxt + x];
        __syncthreads();
#pragma unroll
        for (int i = 0; i < 32; i += 4)
            dst[(size_t)(bxt + y0 + i) * 1024 + byt + x] = __float2half(t[x * 33 + y0 + i]);
        __threadfence();
        __syncthreads();
        if (tid == 0) atomicAdd(&g_cW[z * 8 + (bxt >> 7)], 1);
    } else if (id == 8192) {
        __shared__ int s_isf, s_nb;
        if (tid == 0) { s_isf = 0; s_nb = 0; }
        __syncthreads();
        const int* ip = (const int*)mraw;
#pragma unroll
        for (int q = 0; q < 8; q++) {
            int v = ip[tid * 8 + q];
            if (v == 0x3F800000) atomicExch(&s_isf, 1);
            if (v != 0 && v != 1) atomicExch(&s_nb, 1);
        }
        __syncthreads();
        int mode = s_isf ? 2 : (s_nb ? 1 : 0);
        const unsigned char* bp = (const unsigned char*)mraw;
        const float* fp = (const float*)mraw;
        for (int i = tid; i < B_ * L_; i += 128) {
            unsigned char mv;
            if (mode == 0)      mv = ip[i] != 0;
            else if (mode == 1) mv = bp[i] != 0;
            else                mv = fp[i] != 0.0f;
            g_mask[i] = mv;
        }
        __threadfence();
        __syncthreads();
        if (tid == 0) atomicAdd(&g_cM[0], 1);
    } else if (id < 8961) {
        int a = id - 8193;
        int n_idx = a / 96;
        int rem = a % 96;
        int mode = rem / 32;
        int m_idx = rem % 32;
        if (tid == 0) {
            spin_ge(&g_cX[m_idx], 128);
            spin_ge(&g_cW[mode * 8 + n_idx], 128);
            __threadfence();
        }
        __syncthreads();
        proj_body(mode, m_idx, n_idx, smp, b0, b1, b2, b3, nullptr);
    } else if (id < 9473) {
        int a = id - 8961;
        int n_pair = a / 64;
        int rem = a % 64;
        int hsel = rem & 1;
        int b = (rem >> 1) & 1;
        int qt = rem >> 2;
        int h = n_pair * 2 + hsel;
        int bh = b * 16 + h;
        if (tid == 0) {
            spin_ge(&g_cM[0], 1);
            spin_ge(&g_cQ[(b * 16 + qt) * 8 + n_pair], 1);
            spin_ge(&g_cK[b * 8 + n_pair], 16);
            spin_ge(&g_cV[b * 8 + n_pair], 16);
            __threadfence();
        }
        __syncthreads();
        attn_body(qt, bh, smp);
    } else {
        int o = id - 9473;
        int m_idx = o & 31;
        int n_idx = o >> 5;
        if (tid == 0) {
            spin_ge(&g_cW[24 + n_idx], 128);
            spin_ge(&g_cA[m_idx], 16);
            __threadfence();
        }
        __syncthreads();
        proj_body(3, m_idx, n_idx, smp, b0, b1, b2, b3, Cout);
    }
}

// ---------------------------------------------------------------------------
extern "C" void kernel_launch(void* const* d_in, const int* in_sizes, int n_in,
                              void* d_out, int out_size)
{
    (void)in_sizes; (void)n_in; (void)out_size;
    const float* x_q  = (const float*)d_in[0];
    const float* x_kv = (const float*)d_in[1];
    const void*  mraw = d_in[2];
    const float* wq = (const float*)d_in[3];
    const float* bq = (const float*)d_in[4];
    const float* wk = (const float*)d_in[5];
    const float* bk = (const float*)d_in[6];
    const float* wv = (const float*)d_in[7];
    const float* bv = (const float*)d_in[8];
    const float* wo = (const float*)d_in[9];
    const float* bo = (const float*)d_in[10];
    float* out = (float*)d_out;

    static int attr_done = 0;
    if (!attr_done) {
        cudaFuncSetAttribute(mega, cudaFuncAttributeMaxDynamicSharedMemorySize, PR_SMEM);
        attr_done = 1;
    }

    reset_cnt<<<1, 512>>>();
    mega<<<9729, 128, PR_SMEM>>>(x_q, x_kv, wq, wk, wv, wo, mraw,
                                 bq, bk, bv, bo, out);
}